// round 5
// baseline (speedup 1.0000x reference)
#include <cuda_runtime.h>

// PixelShuffle / depth-to-space, R=2, feature-major grouping.
// in : [B=8, X=256, Y=256, C=256] fp32
// out: [B, 2X=512, 2Y=512, F=64]  fp32
// out[b, 2x+i, 2y+j, f] = in[b, x, y, 4f + 2i + j]
//
// Grid-stride persistent form: one wave (152 SMs x 8 CTAs), each thread loops
// ~28 iterations. Loads for iter k+1 overlap store drain of iter k, keeping
// the outstanding-load pool full instead of sawtoothing per-CTA across ~28
// launch waves.
//
// Mapping (unchanged from the 157.7us baseline): 16 threads per input pixel;
// thread t loads channels [16t,16t+16) as 4x LDG.128 (warp reads 2KB contig),
// writes 4x STG.128, one per (i,j) phase. Default cache ops (.cs measured
// slower: L1 churn, DRAM 86->79%). All offsets fit in 32 bits.

static constexpr int X = 256;
static constexpr int Y = 256;
static constexpr int C = 256;   // = 64 features * 4
static constexpr int THREADS = 256;
static constexpr int GRID = 152 * 8;   // GB300: 152 SMs, occ 8 @ 30 regs

__global__ void __launch_bounds__(THREADS, 8)
pixel_shuffle_kernel(const float4* __restrict__ in, float4* __restrict__ out,
                     unsigned total) {
    const unsigned stride = GRID * THREADS;

    for (unsigned g = blockIdx.x * THREADS + threadIdx.x; g < total; g += stride) {
        const unsigned t = g & 15u;           // 16-channel chunk within pixel
        const unsigned p = g >> 4;            // input pixel id: b*65536 + x*256 + y

        const unsigned y = p & 255u;
        const unsigned x = (p >> 8) & 255u;
        const unsigned b = p >> 16;

        // ---- load: 16 contiguous channels = 4 float4 ----
        const float4* ip = in + (size_t)p * (C / 4) + t * 4;
        const float4 v0 = ip[0];
        const float4 v1 = ip[1];
        const float4 v2 = ip[2];
        const float4 v3 = ip[3];

        // v{k}.c = channel 16t + 4k + c  (feature 4t+k, phase c = 2i + j)

        // ---- store: one float4 per (i,j) output row ----
        // out float4 index: base = ((b*512 + 2x)*512 + 2y)*16 + t
        const unsigned obase = (((b * (2 * X) + 2 * x) * (2 * Y)) + 2 * y) * 16 + t;
        const unsigned ROWI = (2 * Y) * 16;   // +i stride (one output X-row)
        const unsigned ROWJ = 16;             // +j stride (one output Y-row)

        out[obase]               = make_float4(v0.x, v1.x, v2.x, v3.x); // i=0,j=0
        out[obase + ROWJ]        = make_float4(v0.y, v1.y, v2.y, v3.y); // i=0,j=1
        out[obase + ROWI]        = make_float4(v0.z, v1.z, v2.z, v3.z); // i=1,j=0
        out[obase + ROWI + ROWJ] = make_float4(v0.w, v1.w, v2.w, v3.w); // i=1,j=1
    }
}

extern "C" void kernel_launch(void* const* d_in, const int* in_sizes, int n_in,
                              void* d_out, int out_size) {
    (void)n_in; (void)out_size;
    const float4* in = (const float4*)d_in[0];
    float4* out = (float4*)d_out;

    const unsigned total = (unsigned)((long long)in_sizes[0] / 16);  // work items

    pixel_shuffle_kernel<<<GRID, THREADS>>>(in, out, total);
}

// round 6
// speedup vs baseline: 1.1051x; 1.1051x over previous
#include <cuda_runtime.h>

// PixelShuffle / depth-to-space, R=2, feature-major grouping.
// in : [B=8, X=256, Y=256, C=256] fp32
// out: [B, 2X=512, 2Y=512, F=64]  fp32
// out[b, 2x+i, 2y+j, f] = in[b, x, y, 4f + 2i + j]
//
// One-shot CTAs (persistent loop measured 174us vs 157.7us: loop serializes
// loads behind prior stores; HW CTA scheduler pipelines better). This version
// unrolls x2 in straight line: each thread handles items g and g+half, with
// ALL 8 LDG.128 front-batched before the 8 STG.128 -> per-warp MLP 4 -> 8.
//
// Per item: 16 threads per input pixel; thread t loads channels [16t,16t+16)
// (warp reads 2KB contiguous), writes 4x STG.128, one per (i,j) phase (1KB
// contiguous run per i-phase per warp). Default cache ops (.cs measured
// slower). All offsets fit in 32 bits.

static constexpr int X = 256;
static constexpr int Y = 256;
static constexpr int C = 256;   // = 64 features * 4
static constexpr int THREADS = 256;

__device__ __forceinline__ void addrs(unsigned g, const float4** ip, unsigned* ob) {
    const unsigned t = g & 15u;
    const unsigned p = g >> 4;            // b*65536 + x*256 + y
    const unsigned y = p & 255u;
    const unsigned x = (p >> 8) & 255u;
    const unsigned b = p >> 16;
    *ip = (const float4*)0 + (size_t)p * (C / 4) + t * 4;   // offset only
    *ob = (((b * (2 * X) + 2 * x) * (2 * Y)) + 2 * y) * 16 + t;
}

__global__ void pixel_shuffle_kernel(const float4* __restrict__ in,
                                     float4* __restrict__ out,
                                     unsigned half) {
    const unsigned g0 = blockIdx.x * THREADS + threadIdx.x;
    const unsigned g1 = g0 + half;

    // ---- addresses ----
    const unsigned t0 = g0 & 15u, t1 = g1 & 15u;
    const unsigned p0 = g0 >> 4,  p1 = g1 >> 4;

    const float4* ip0 = in + (size_t)p0 * (C / 4) + t0 * 4;
    const float4* ip1 = in + (size_t)p1 * (C / 4) + t1 * 4;

    // ---- front-batch all 8 loads (MLP=8) ----
    const float4 a0 = ip0[0];
    const float4 a1 = ip0[1];
    const float4 a2 = ip0[2];
    const float4 a3 = ip0[3];
    const float4 b0 = ip1[0];
    const float4 b1 = ip1[1];
    const float4 b2 = ip1[2];
    const float4 b3 = ip1[3];

    const unsigned ROWI = (2 * Y) * 16;   // +i stride (one output X-row)
    const unsigned ROWJ = 16;             // +j stride (one output Y-row)

    // item 0 output base
    {
        const unsigned y = p0 & 255u, x = (p0 >> 8) & 255u, b = p0 >> 16;
        const unsigned ob = (((b * (2 * X) + 2 * x) * (2 * Y)) + 2 * y) * 16 + t0;
        out[ob]               = make_float4(a0.x, a1.x, a2.x, a3.x); // i=0,j=0
        out[ob + ROWJ]        = make_float4(a0.y, a1.y, a2.y, a3.y); // i=0,j=1
        out[ob + ROWI]        = make_float4(a0.z, a1.z, a2.z, a3.z); // i=1,j=0
        out[ob + ROWI + ROWJ] = make_float4(a0.w, a1.w, a2.w, a3.w); // i=1,j=1
    }
    // item 1 output base
    {
        const unsigned y = p1 & 255u, x = (p1 >> 8) & 255u, b = p1 >> 16;
        const unsigned ob = (((b * (2 * X) + 2 * x) * (2 * Y)) + 2 * y) * 16 + t1;
        out[ob]               = make_float4(b0.x, b1.x, b2.x, b3.x);
        out[ob + ROWJ]        = make_float4(b0.y, b1.y, b2.y, b3.y);
        out[ob + ROWI]        = make_float4(b0.z, b1.z, b2.z, b3.z);
        out[ob + ROWI + ROWJ] = make_float4(b0.w, b1.w, b2.w, b3.w);
    }
}

extern "C" void kernel_launch(void* const* d_in, const int* in_sizes, int n_in,
                              void* d_out, int out_size) {
    (void)n_in; (void)out_size;
    const float4* in = (const float4*)d_in[0];
    float4* out = (float4*)d_out;

    const long long total_items = (long long)in_sizes[0] / 16;  // 16 floats/item
    const unsigned half = (unsigned)(total_items / 2);
    const int grid = (int)(half / THREADS);                     // exact: power of 2

    pixel_shuffle_kernel<<<grid, THREADS>>>(in, out, half);
}